// round 1
// baseline (speedup 1.0000x reference)
#include <cuda_runtime.h>
#include <math.h>

#define N_DOC 10000
#define N_WORD 20000
#define N_ENT 10000
#define N_POS 60
#define DIM 128
#define D_POS_IN 60
#define D_WEMB 300
#define E11 320000
#define E22 160000
#define E33 3600
#define E01 300000
#define E02 100000
#define E03 150000

// ---------------- scratch (static device globals; no allocation allowed) ----------------
__device__ int   g_rp11[N_WORD + 1]; __device__ int g_cu11[N_WORD]; __device__ int g_cs11[E11]; __device__ float g_vs11[E11];
__device__ int   g_rp22[N_ENT + 1];  __device__ int g_cu22[N_ENT];  __device__ int g_cs22[E22]; __device__ float g_vs22[E22];
__device__ int   g_rp33[N_POS + 1];  __device__ int g_cu33[N_POS];  __device__ int g_cs33[E33]; __device__ float g_vs33[E33];
__device__ int   g_rp01[N_DOC + 1];  __device__ int g_cu01[N_DOC];  __device__ int g_cs01[E01]; __device__ float g_vs01[E01];
__device__ int   g_rp02[N_DOC + 1];  __device__ int g_cu02[N_DOC];  __device__ int g_cs02[E02]; __device__ float g_vs02[E02];
__device__ int   g_rp03[N_DOC + 1];  __device__ int g_cu03[N_DOC];  __device__ int g_cs03[E03]; __device__ float g_vs03[E03];

__device__ float g_x1[N_WORD * DIM];   // h1 after layer 1
__device__ float g_t[N_WORD * DIM];    // GEMM temp (sized for largest)
__device__ float g_h1[N_WORD * DIM];   // h1 final
__device__ float g_x2[N_ENT * DIM];
__device__ float g_h2[N_ENT * DIM];
__device__ float g_x3[N_POS * DIM];
__device__ float g_h3t[N_POS * DIM];
__device__ float g_h3[N_POS * DIM];

// ---------------- CSR build ----------------
__global__ void k_zero_int(int* p, int n) {
    int i = blockIdx.x * blockDim.x + threadIdx.x;
    if (i < n) p[i] = 0;
}

__global__ void k_hist(const int* __restrict__ rows, int E, int* __restrict__ cnt) {
    int e = blockIdx.x * blockDim.x + threadIdx.x;
    if (e < E) atomicAdd(&cnt[rows[e]], 1);
}

// counts live in `cursor` on entry; on exit cursor[i] = exclusive prefix (start offsets),
// rowptr[i] = exclusive prefix, rowptr[n] = total.
__global__ void k_scan(int* __restrict__ cursor, int* __restrict__ rowptr, int n) {
    __shared__ int sh[1024];
    __shared__ int carry;
    int tid = threadIdx.x;
    if (tid == 0) carry = 0;
    __syncthreads();
    for (int base = 0; base < n; base += 1024) {
        int i = base + tid;
        int v = (i < n) ? cursor[i] : 0;
        sh[tid] = v;
        __syncthreads();
        for (int off = 1; off < 1024; off <<= 1) {
            int t = (tid >= off) ? sh[tid - off] : 0;
            __syncthreads();
            sh[tid] += t;
            __syncthreads();
        }
        if (i < n) {
            int excl = carry + sh[tid] - v;
            cursor[i] = excl;
            rowptr[i] = excl;
        }
        __syncthreads();
        if (tid == 1023) carry += sh[1023];
        __syncthreads();
    }
    if (tid == 0) rowptr[n] = carry;
}

__global__ void k_scatter(const int* __restrict__ rows, const int* __restrict__ cols,
                          const float* __restrict__ vals, int E,
                          int* __restrict__ cursor, int* __restrict__ colsS,
                          float* __restrict__ valsS) {
    int e = blockIdx.x * blockDim.x + threadIdx.x;
    if (e < E) {
        int slot = atomicAdd(&cursor[rows[e]], 1);
        colsS[slot] = cols[e];
        valsS[slot] = vals[e];
    }
}

// ---------------- spMM (gather form, one 128-thread block per output row) ----------------
__global__ void k_spmm128_relu(const int* __restrict__ rowptr, const int* __restrict__ cols,
                               const float* __restrict__ vals, const float* __restrict__ x,
                               float* __restrict__ y) {
    int r = blockIdx.x, c = threadIdx.x;
    int s = rowptr[r], e = rowptr[r + 1];
    float acc = 0.f;
    int i = s;
    for (; i + 3 < e; i += 4) {
        int c0 = cols[i], c1 = cols[i + 1], c2 = cols[i + 2], c3 = cols[i + 3];
        float v0 = vals[i], v1 = vals[i + 1], v2 = vals[i + 2], v3 = vals[i + 3];
        acc = fmaf(v0, x[(size_t)c0 * DIM + c], acc);
        acc = fmaf(v1, x[(size_t)c1 * DIM + c], acc);
        acc = fmaf(v2, x[(size_t)c2 * DIM + c], acc);
        acc = fmaf(v3, x[(size_t)c3 * DIM + c], acc);
    }
    for (; i < e; i++) acc = fmaf(vals[i], x[(size_t)cols[i] * DIM + c], acc);
    y[(size_t)r * DIM + c] = fmaxf(acc, 0.f);
}

__global__ void k_spmm128_norm(const int* __restrict__ rowptr, const int* __restrict__ cols,
                               const float* __restrict__ vals, const float* __restrict__ x,
                               float* __restrict__ out) {
    int r = blockIdx.x, c = threadIdx.x;
    int s = rowptr[r], e = rowptr[r + 1];
    float acc = 0.f;
    int i = s;
    for (; i + 3 < e; i += 4) {
        int c0 = cols[i], c1 = cols[i + 1], c2 = cols[i + 2], c3 = cols[i + 3];
        float v0 = vals[i], v1 = vals[i + 1], v2 = vals[i + 2], v3 = vals[i + 3];
        acc = fmaf(v0, x[(size_t)c0 * DIM + c], acc);
        acc = fmaf(v1, x[(size_t)c1 * DIM + c], acc);
        acc = fmaf(v2, x[(size_t)c2 * DIM + c], acc);
        acc = fmaf(v3, x[(size_t)c3 * DIM + c], acc);
    }
    for (; i < e; i++) acc = fmaf(vals[i], x[(size_t)cols[i] * DIM + c], acc);
    __shared__ float red[128];
    red[c] = acc * acc;
    __syncthreads();
    for (int off = 64; off > 0; off >>= 1) {
        if (c < off) red[c] += red[c + off];
        __syncthreads();
    }
    float scale = 1.f / (sqrtf(red[0]) + 1e-9f);
    out[(size_t)r * DIM + c] = acc * scale;
}

// a02 aggregation with virtual concat [h2 (128) | word_emb (300)], L2-normalized over 428.
__global__ void k_spmm_out2(const int* __restrict__ rowptr, const int* __restrict__ cols,
                            const float* __restrict__ vals, const float* __restrict__ h2,
                            const float* __restrict__ wemb, float* __restrict__ out) {
    int r = blockIdx.x, t = threadIdx.x;  // 512 threads, 428 active
    int s = rowptr[r], e = rowptr[r + 1];
    float acc = 0.f;
    if (t < DIM) {
        for (int i = s; i < e; i++) acc = fmaf(vals[i], h2[(size_t)cols[i] * DIM + t], acc);
    } else if (t < DIM + D_WEMB) {
        int tc = t - DIM;
        for (int i = s; i < e; i++) acc = fmaf(vals[i], wemb[(size_t)cols[i] * D_WEMB + tc], acc);
    }
    __shared__ float red[512];
    red[t] = acc * acc;
    __syncthreads();
    for (int off = 256; off > 0; off >>= 1) {
        if (t < off) red[t] += red[t + off];
        __syncthreads();
    }
    float scale = 1.f / (sqrtf(red[0]) + 1e-9f);
    if (t < DIM + D_WEMB) out[(size_t)r * (DIM + D_WEMB) + t] = acc * scale;
}

// ---------------- small dense GEMM: y[n,128] = x[n,K] @ W[K,128] + b ----------------
template <int K>
__global__ void k_gemm_bias(const float* __restrict__ x, const float* __restrict__ W,
                            const float* __restrict__ b, float* __restrict__ y, int nrows) {
    __shared__ float xs[16 * K];
    int t = threadIdx.x;  // output column, 128 threads
    int r0 = blockIdx.x * 16;
    for (int idx = t; idx < 16 * K; idx += 128) {
        int rr = idx / K;
        xs[idx] = (r0 + rr < nrows) ? x[(size_t)r0 * K + idx] : 0.f;
    }
    __syncthreads();
    float bt = b[t];
    float acc[16];
#pragma unroll
    for (int r = 0; r < 16; r++) acc[r] = bt;
    for (int k = 0; k < K; k++) {
        float w = W[k * DIM + t];
#pragma unroll
        for (int r = 0; r < 16; r++) acc[r] = fmaf(xs[r * K + k], w, acc[r]);
    }
    int nr = nrows - r0;
    if (nr > 16) nr = 16;
    for (int r = 0; r < nr; r++) y[(size_t)(r0 + r) * DIM + t] = acc[r];
}

// ---------------- host ----------------
template <typename T>
static T* sym(const void* s) {
    void* p = nullptr;
    cudaGetSymbolAddress(&p, s);
    return (T*)p;
}

static void build_csr(const int* rows, const int* cols, const float* vals, int E, int n,
                      int* rowptr, int* cursor, int* colsS, float* valsS) {
    k_zero_int<<<(n + 255) / 256, 256>>>(cursor, n);
    k_hist<<<(E + 255) / 256, 256>>>(rows, E, cursor);
    k_scan<<<1, 1024>>>(cursor, rowptr, n);
    k_scatter<<<(E + 255) / 256, 256>>>(rows, cols, vals, E, cursor, colsS, valsS);
}

extern "C" void kernel_launch(void* const* d_in, const int* in_sizes, int n_in,
                              void* d_out, int out_size) {
    const float* f1 = (const float*)d_in[0];
    const float* f2 = (const float*)d_in[1];
    const float* f3 = (const float*)d_in[2];
    const float* wemb = (const float*)d_in[3];
    const int* a11_r = (const int*)d_in[4];  const int* a11_c = (const int*)d_in[5];  const float* a11_v = (const float*)d_in[6];
    const int* a22_r = (const int*)d_in[7];  const int* a22_c = (const int*)d_in[8];  const float* a22_v = (const float*)d_in[9];
    const int* a33_r = (const int*)d_in[10]; const int* a33_c = (const int*)d_in[11]; const float* a33_v = (const float*)d_in[12];
    const int* a01_r = (const int*)d_in[13]; const int* a01_c = (const int*)d_in[14]; const float* a01_v = (const float*)d_in[15];
    const int* a02_r = (const int*)d_in[16]; const int* a02_c = (const int*)d_in[17]; const float* a02_v = (const float*)d_in[18];
    const int* a03_r = (const int*)d_in[19]; const int* a03_c = (const int*)d_in[20]; const float* a03_v = (const float*)d_in[21];
    const float* W3 = (const float*)d_in[22];   const float* b3 = (const float*)d_in[23];
    const float* W1_2 = (const float*)d_in[24]; const float* b1_2 = (const float*)d_in[25];
    const float* W2_2 = (const float*)d_in[26]; const float* b2_2 = (const float*)d_in[27];
    const float* W3_2 = (const float*)d_in[28]; const float* b3_2 = (const float*)d_in[29];

    int* rp11 = sym<int>(g_rp11); int* cu11 = sym<int>(g_cu11); int* cs11 = sym<int>(g_cs11); float* vs11 = sym<float>(g_vs11);
    int* rp22 = sym<int>(g_rp22); int* cu22 = sym<int>(g_cu22); int* cs22 = sym<int>(g_cs22); float* vs22 = sym<float>(g_vs22);
    int* rp33 = sym<int>(g_rp33); int* cu33 = sym<int>(g_cu33); int* cs33 = sym<int>(g_cs33); float* vs33 = sym<float>(g_vs33);
    int* rp01 = sym<int>(g_rp01); int* cu01 = sym<int>(g_cu01); int* cs01 = sym<int>(g_cs01); float* vs01 = sym<float>(g_vs01);
    int* rp02 = sym<int>(g_rp02); int* cu02 = sym<int>(g_cu02); int* cs02 = sym<int>(g_cs02); float* vs02 = sym<float>(g_vs02);
    int* rp03 = sym<int>(g_rp03); int* cu03 = sym<int>(g_cu03); int* cs03 = sym<int>(g_cs03); float* vs03 = sym<float>(g_vs03);

    float* x1 = sym<float>(g_x1);   float* t = sym<float>(g_t);   float* h1 = sym<float>(g_h1);
    float* x2 = sym<float>(g_x2);   float* h2 = sym<float>(g_h2);
    float* x3 = sym<float>(g_x3);   float* h3t = sym<float>(g_h3t); float* h3 = sym<float>(g_h3);

    float* out = (float*)d_out;
    float* out1 = out;
    float* out2 = out + (size_t)N_DOC * DIM;
    float* out3 = out + (size_t)N_DOC * (DIM + DIM + D_WEMB);

    // --- CSR builds (all 6 graphs) ---
    build_csr(a11_r, a11_c, a11_v, E11, N_WORD, rp11, cu11, cs11, vs11);
    build_csr(a22_r, a22_c, a22_v, E22, N_ENT, rp22, cu22, cs22, vs22);
    build_csr(a33_r, a33_c, a33_v, E33, N_POS, rp33, cu33, cs33, vs33);
    build_csr(a01_r, a01_c, a01_v, E01, N_DOC, rp01, cu01, cs01, vs01);
    build_csr(a02_r, a02_c, a02_v, E02, N_DOC, rp02, cu02, cs02, vs02);
    build_csr(a03_r, a03_c, a03_v, E03, N_DOC, rp03, cu03, cs03, vs03);

    // --- type 1 (words): relu(A11 f1) -> relu(A11 (h W1_2 + b)) ---
    k_spmm128_relu<<<N_WORD, 128>>>(rp11, cs11, vs11, f1, x1);
    k_gemm_bias<128><<<(N_WORD + 15) / 16, 128>>>(x1, W1_2, b1_2, t, N_WORD);
    k_spmm128_relu<<<N_WORD, 128>>>(rp11, cs11, vs11, t, h1);

    // --- type 2 (entities) ---
    k_spmm128_relu<<<N_ENT, 128>>>(rp22, cs22, vs22, f2, x2);
    k_gemm_bias<128><<<(N_ENT + 15) / 16, 128>>>(x2, W2_2, b2_2, t, N_ENT);
    k_spmm128_relu<<<N_ENT, 128>>>(rp22, cs22, vs22, t, h2);

    // --- type 3 (POS): full GCN (W3,b3) -> GCN_2 ---
    k_gemm_bias<60><<<(N_POS + 15) / 16, 128>>>(f3, W3, b3, x3, N_POS);
    k_spmm128_relu<<<N_POS, 128>>>(rp33, cs33, vs33, x3, h3t);
    k_gemm_bias<128><<<(N_POS + 15) / 16, 128>>>(h3t, W3_2, b3_2, x3, N_POS);
    k_spmm128_relu<<<N_POS, 128>>>(rp33, cs33, vs33, x3, h3);

    // --- doc aggregation + L2 normalization ---
    k_spmm128_norm<<<N_DOC, 128>>>(rp01, cs01, vs01, h1, out1);
    k_spmm_out2<<<N_DOC, 512>>>(rp02, cs02, vs02, h2, wemb, out2);
    k_spmm128_norm<<<N_DOC, 128>>>(rp03, cs03, vs03, h3, out3);
}

// round 2
// speedup vs baseline: 1.5525x; 1.5525x over previous
#include <cuda_runtime.h>
#include <math.h>

#define N_DOC 10000
#define N_WORD 20000
#define N_ENT 10000
#define N_POS 60
#define DIM 128
#define D_POS_IN 60
#define D_WEMB 300
#define E11 320000
#define E22 160000
#define E33 3600
#define E01 300000
#define E02 100000
#define E03 150000

// merged offsets (compile time)
enum { CU11 = 0, CU22 = 20000, CU33 = 30000, CU01 = 30060, CU02 = 40060, CU03 = 50060, CU_TOT = 60060 };
enum { RP11 = 0, RP22 = 20001, RP33 = 30002, RP01 = 30063, RP02 = 40064, RP03 = 50065, RP_TOT = 60066 };
enum { EO11 = 0, EO22 = 320000, EO33 = 480000, EO01 = 483600, EO02 = 783600, EO03 = 883600, E_TOT = 1033600 };

// hist/scatter block ranges (256 threads/block)
enum { HB11 = 1250, HB22 = 1875, HB33 = 1890, HB01 = 3062, HB02 = 3453, HB03 = 4039 };

// ---------------- scratch ----------------
__device__ int   g_cu[CU_TOT];
__device__ int   g_rp[RP_TOT];
__device__ int   g_cols[E_TOT];
__device__ float g_vals[E_TOT];

__device__ float g_h1a[N_WORD * DIM];
__device__ float g_t1[N_WORD * DIM];
__device__ float g_h1[N_WORD * DIM];
__device__ float g_h2a[N_ENT * DIM];
__device__ float g_t2[N_ENT * DIM];
__device__ float g_h2[N_ENT * DIM];
__device__ float g_t3a[N_POS * DIM];
__device__ float g_t3b[N_POS * DIM];
__device__ float g_h3[N_POS * DIM];

// ---------------- CSR build ----------------
__global__ void k_zero() {
    int i = blockIdx.x * blockDim.x + threadIdx.x;
    if (i < CU_TOT) g_cu[i] = 0;
}

__global__ void k_hist_all(const int* __restrict__ r11, const int* __restrict__ r22,
                           const int* __restrict__ r33, const int* __restrict__ r01,
                           const int* __restrict__ r02, const int* __restrict__ r03) {
    int b = blockIdx.x, t = threadIdx.x;
    const int* rows; int E, off, b0;
    if (b < HB11)      { rows = r11; E = E11; off = CU11; b0 = 0; }
    else if (b < HB22) { rows = r22; E = E22; off = CU22; b0 = HB11; }
    else if (b < HB33) { rows = r33; E = E33; off = CU33; b0 = HB22; }
    else if (b < HB01) { rows = r01; E = E01; off = CU01; b0 = HB33; }
    else if (b < HB02) { rows = r02; E = E02; off = CU02; b0 = HB01; }
    else               { rows = r03; E = E03; off = CU03; b0 = HB02; }
    int e = (b - b0) * 256 + t;
    if (e < E) atomicAdd(&g_cu[off + rows[e]], 1);
}

__global__ void k_scan_all() {
    __shared__ int wsum[32];
    const int ns[6]  = {N_WORD, N_ENT, N_POS, N_DOC, N_DOC, N_DOC};
    const int cuo[6] = {CU11, CU22, CU33, CU01, CU02, CU03};
    const int rpo[6] = {RP11, RP22, RP33, RP01, RP02, RP03};
    int g = blockIdx.x;
    int n = ns[g];
    int* cnt = g_cu + cuo[g];
    int* rp  = g_rp + rpo[g];
    int tid = threadIdx.x;  // 1024
    int chunk = (n + 1023) >> 10;
    int base = tid * chunk;
    int end = base + chunk; if (end > n) end = n;
    int s = 0;
    for (int i = base; i < end && i >= base; i++) s += cnt[i];
    // block-wide inclusive scan of per-thread sums
    int lane = tid & 31, w = tid >> 5;
    int v = s;
#pragma unroll
    for (int o = 1; o < 32; o <<= 1) { int u = __shfl_up_sync(~0u, v, o); if (lane >= o) v += u; }
    if (lane == 31) wsum[w] = v;
    __syncthreads();
    if (w == 0) {
        int x = wsum[lane];
#pragma unroll
        for (int o = 1; o < 32; o <<= 1) { int u = __shfl_up_sync(~0u, x, o); if (lane >= o) x += u; }
        wsum[lane] = x;
    }
    __syncthreads();
    int excl = v - s + (w > 0 ? wsum[w - 1] : 0);
    int run = excl;
    for (int i = base; i < end && i >= base; i++) {
        int c = cnt[i];
        cnt[i] = run;
        rp[i] = run;
        run += c;
    }
    if (end == n || base >= n) rp[n] = run;  // run == total for all such threads
}

__global__ void k_scatter_all(const int* __restrict__ r11, const int* __restrict__ c11, const float* __restrict__ v11,
                              const int* __restrict__ r22, const int* __restrict__ c22, const float* __restrict__ v22,
                              const int* __restrict__ r33, const int* __restrict__ c33, const float* __restrict__ v33,
                              const int* __restrict__ r01, const int* __restrict__ c01, const float* __restrict__ v01,
                              const int* __restrict__ r02, const int* __restrict__ c02, const float* __restrict__ v02,
                              const int* __restrict__ r03, const int* __restrict__ c03, const float* __restrict__ v03) {
    int b = blockIdx.x, t = threadIdx.x;
    const int* rows; const int* cols; const float* vals; int E, cuoff, eoff, b0;
    if (b < HB11)      { rows = r11; cols = c11; vals = v11; E = E11; cuoff = CU11; eoff = EO11; b0 = 0; }
    else if (b < HB22) { rows = r22; cols = c22; vals = v22; E = E22; cuoff = CU22; eoff = EO22; b0 = HB11; }
    else if (b < HB33) { rows = r33; cols = c33; vals = v33; E = E33; cuoff = CU33; eoff = EO33; b0 = HB22; }
    else if (b < HB01) { rows = r01; cols = c01; vals = v01; E = E01; cuoff = CU01; eoff = EO01; b0 = HB33; }
    else if (b < HB02) { rows = r02; cols = c02; vals = v02; E = E02; cuoff = CU02; eoff = EO02; b0 = HB01; }
    else               { rows = r03; cols = c03; vals = v03; E = E03; cuoff = CU03; eoff = EO03; b0 = HB02; }
    int e = (b - b0) * 256 + t;
    if (e < E) {
        int slot = atomicAdd(&g_cu[cuoff + rows[e]], 1);
        g_cols[eoff + slot] = cols[e];
        g_vals[eoff + slot] = vals[e];
    }
}

// ---------------- spMM core: warp computes one row, lane holds 4 columns ----------------
__device__ __forceinline__ float4 spmm_row_f4(const int* __restrict__ rp, const int* __restrict__ cs,
                                              const float* __restrict__ vs, const float4* __restrict__ x4,
                                              int row, int lane) {
    int s = rp[row], e = rp[row + 1];
    float4 acc = make_float4(0.f, 0.f, 0.f, 0.f);
    int i = s;
    for (; i + 1 < e; i += 2) {
        int c0 = cs[i], c1 = cs[i + 1];
        float v0 = vs[i], v1 = vs[i + 1];
        float4 a = x4[(size_t)c0 * 32 + lane];
        float4 b = x4[(size_t)c1 * 32 + lane];
        acc.x = fmaf(v0, a.x, fmaf(v1, b.x, acc.x));
        acc.y = fmaf(v0, a.y, fmaf(v1, b.y, acc.y));
        acc.z = fmaf(v0, a.z, fmaf(v1, b.z, acc.z));
        acc.w = fmaf(v0, a.w, fmaf(v1, b.w, acc.w));
    }
    if (i < e) {
        int c0 = cs[i]; float v0 = vs[i];
        float4 a = x4[(size_t)c0 * 32 + lane];
        acc.x = fmaf(v0, a.x, acc.x);
        acc.y = fmaf(v0, a.y, acc.y);
        acc.z = fmaf(v0, a.z, acc.z);
        acc.w = fmaf(v0, a.w, acc.w);
    }
    return acc;
}

__device__ __forceinline__ void store_relu_f4(float4 acc, float* __restrict__ y, int row, int lane) {
    float4 r = make_float4(fmaxf(acc.x, 0.f), fmaxf(acc.y, 0.f), fmaxf(acc.z, 0.f), fmaxf(acc.w, 0.f));
    ((float4*)y)[(size_t)row * 32 + lane] = r;
}

__device__ __forceinline__ void store_norm_f4(float4 acc, float* __restrict__ y, int row, int lane) {
    float sq = acc.x * acc.x + acc.y * acc.y + acc.z * acc.z + acc.w * acc.w;
#pragma unroll
    for (int o = 16; o > 0; o >>= 1) sq += __shfl_xor_sync(~0u, sq, o);
    float s = 1.f / (sqrtf(sq) + 1e-9f);
    ((float4*)y)[(size_t)row * 32 + lane] = make_float4(acc.x * s, acc.y * s, acc.z * s, acc.w * s);
}

// ---------------- 32-row GEMM tile: y[r0..r0+32,128] = x[.,128] @ W[128,128] + b ----------------
__device__ __forceinline__ void gemm32(const float* __restrict__ x, const float* __restrict__ W,
                                       const float* __restrict__ bias, float* __restrict__ y,
                                       int nrows, int r0, float* xs) {
    int t = threadIdx.x;
    float4* xs4 = (float4*)xs;
    const float4* x4 = (const float4*)x;
    for (int i = t; i < 32 * 32; i += 256) {
        int r = i >> 5;
        int gr = r0 + r;
        xs4[i] = (gr < nrows) ? x4[(size_t)gr * 32 + (i & 31)] : make_float4(0.f, 0.f, 0.f, 0.f);
    }
    __syncthreads();
    int col = t & 127, half = t >> 7;
    float bt = bias[col];
    float acc[16];
#pragma unroll
    for (int r = 0; r < 16; r++) acc[r] = bt;
    const float4* xs4c = (const float4*)xs;
    for (int k4 = 0; k4 < 32; k4++) {
        float w0 = W[(k4 * 4 + 0) * 128 + col];
        float w1 = W[(k4 * 4 + 1) * 128 + col];
        float w2 = W[(k4 * 4 + 2) * 128 + col];
        float w3 = W[(k4 * 4 + 3) * 128 + col];
#pragma unroll
        for (int r = 0; r < 16; r++) {
            float4 xv = xs4c[(half * 16 + r) * 32 + k4];
            acc[r] = fmaf(xv.x, w0, acc[r]);
            acc[r] = fmaf(xv.y, w1, acc[r]);
            acc[r] = fmaf(xv.z, w2, acc[r]);
            acc[r] = fmaf(xv.w, w3, acc[r]);
        }
    }
#pragma unroll
    for (int r = 0; r < 16; r++) {
        int gr = r0 + half * 16 + r;
        if (gr < nrows) y[(size_t)gr * 128 + col] = acc[r];
    }
}

// ---------------- Stage A: spmm1(t1) + spmm1(t2) + gemm1(t3, K=60) ----------------
__global__ void k_stageA(const float* __restrict__ f1, const float* __restrict__ f2,
                         const float* __restrict__ f3, const float* __restrict__ W3,
                         const float* __restrict__ b3) {
    int b = blockIdx.x, t = threadIdx.x, lane = t & 31, w = t >> 5;
    if (b < 2500) {
        int row = b * 8 + w;
        float4 acc = spmm_row_f4(g_rp + RP11, g_cols + EO11, g_vals + EO11, (const float4*)f1, row, lane);
        store_relu_f4(acc, g_h1a, row, lane);
    } else if (b < 3750) {
        int row = (b - 2500) * 8 + w;
        float4 acc = spmm_row_f4(g_rp + RP22, g_cols + EO22, g_vals + EO22, (const float4*)f2, row, lane);
        store_relu_f4(acc, g_h2a, row, lane);
    } else {
        // type-3 first dense layer: g_t3a = f3 @ W3 + b3  (60x60 @ 60x128)
        for (int idx = t; idx < N_POS * DIM; idx += 256) {
            int r = idx >> 7, c = idx & 127;
            float a = b3[c];
#pragma unroll 4
            for (int k = 0; k < D_POS_IN; k++)
                a = fmaf(f3[r * D_POS_IN + k], W3[k * DIM + c], a);
            g_t3a[idx] = a;
        }
    }
}

// ---------------- Stage B: gemm(t1) + gemm(t2) + spmm1(t3) ----------------
__global__ void k_stageB(const float* __restrict__ W1_2, const float* __restrict__ b1_2,
                         const float* __restrict__ W2_2, const float* __restrict__ b2_2) {
    __shared__ float xs[32 * 128];
    int b = blockIdx.x;
    if (b < 938) {
        if (b < 625) gemm32(g_h1a, W1_2, b1_2, g_t1, N_WORD, b * 32, xs);
        else         gemm32(g_h2a, W2_2, b2_2, g_t2, N_ENT, (b - 625) * 32, xs);
    } else {
        int t = threadIdx.x, lane = t & 31, w = t >> 5;
        int row = (b - 938) * 8 + w;
        if (row < N_POS) {
            float4 acc = spmm_row_f4(g_rp + RP33, g_cols + EO33, g_vals + EO33, (const float4*)g_t3a, row, lane);
            store_relu_f4(acc, g_t3b, row, lane);
        }
    }
}

// ---------------- Stage C: spmm2(t1) + spmm2(t2) + gemm2(t3) ----------------
__global__ void k_stageC(const float* __restrict__ W3_2, const float* __restrict__ b3_2) {
    __shared__ float xs[32 * 128];
    int b = blockIdx.x, t = threadIdx.x, lane = t & 31, w = t >> 5;
    if (b < 2500) {
        int row = b * 8 + w;
        float4 acc = spmm_row_f4(g_rp + RP11, g_cols + EO11, g_vals + EO11, (const float4*)g_t1, row, lane);
        store_relu_f4(acc, g_h1, row, lane);
    } else if (b < 3750) {
        int row = (b - 2500) * 8 + w;
        float4 acc = spmm_row_f4(g_rp + RP22, g_cols + EO22, g_vals + EO22, (const float4*)g_t2, row, lane);
        store_relu_f4(acc, g_h2, row, lane);
    } else {
        gemm32(g_t3b, W3_2, b3_2, g_t3a, N_POS, (b - 3750) * 32, xs);
    }
}

// ---------------- Stage D (512 thr): out1 + out2 + spmm2(t3) ----------------
__global__ void k_stageD(const float* __restrict__ wemb, float* __restrict__ out) {
    __shared__ float red[512];
    int b = blockIdx.x, t = threadIdx.x;
    if (b < 625) {
        int lane = t & 31, w = t >> 5;
        int row = b * 16 + w;
        float4 acc = spmm_row_f4(g_rp + RP01, g_cols + EO01, g_vals + EO01, (const float4*)g_h1, row, lane);
        store_norm_f4(acc, out, row, lane);  // out1 at offset 0
    } else if (b < 10625) {
        int row = b - 625;
        const int* rp = g_rp + RP02;
        const int* cs = g_cols + EO02;
        const float* vs = g_vals + EO02;
        int s = rp[row], e = rp[row + 1];
        float acc = 0.f;
        if (t < DIM) {
            for (int i = s; i < e; i++)
                acc = fmaf(vs[i], g_h2[(size_t)cs[i] * DIM + t], acc);
        } else if (t < DIM + D_WEMB) {
            int tc = t - DIM;
            for (int i = s; i < e; i++)
                acc = fmaf(vs[i], wemb[(size_t)cs[i] * D_WEMB + tc], acc);
        }
        red[t] = acc * acc;
        __syncthreads();
#pragma unroll
        for (int off = 256; off > 0; off >>= 1) {
            if (t < off) red[t] += red[t + off];
            __syncthreads();
        }
        float scale = 1.f / (sqrtf(red[0]) + 1e-9f);
        if (t < DIM + D_WEMB)
            out[(size_t)N_DOC * DIM + (size_t)row * (DIM + D_WEMB) + t] = acc * scale;
    } else {
        int lane = t & 31, w = t >> 5;
        int row = (b - 10625) * 16 + w;
        if (row < N_POS) {
            float4 acc = spmm_row_f4(g_rp + RP33, g_cols + EO33, g_vals + EO33, (const float4*)g_t3a, row, lane);
            store_relu_f4(acc, g_h3, row, lane);
        }
    }
}

// ---------------- Stage E (512 thr): out3 ----------------
__global__ void k_stageE(float* __restrict__ out) {
    int b = blockIdx.x, t = threadIdx.x, lane = t & 31, w = t >> 5;
    int row = b * 16 + w;
    float4 acc = spmm_row_f4(g_rp + RP03, g_cols + EO03, g_vals + EO03, (const float4*)g_h3, row, lane);
    float* out3 = out + (size_t)N_DOC * (DIM + DIM + D_WEMB);
    store_norm_f4(acc, out3, row, lane);
}

// ---------------- host ----------------
extern "C" void kernel_launch(void* const* d_in, const int* in_sizes, int n_in,
                              void* d_out, int out_size) {
    const float* f1 = (const float*)d_in[0];
    const float* f2 = (const float*)d_in[1];
    const float* f3 = (const float*)d_in[2];
    const float* wemb = (const float*)d_in[3];
    const int* a11_r = (const int*)d_in[4];  const int* a11_c = (const int*)d_in[5];  const float* a11_v = (const float*)d_in[6];
    const int* a22_r = (const int*)d_in[7];  const int* a22_c = (const int*)d_in[8];  const float* a22_v = (const float*)d_in[9];
    const int* a33_r = (const int*)d_in[10]; const int* a33_c = (const int*)d_in[11]; const float* a33_v = (const float*)d_in[12];
    const int* a01_r = (const int*)d_in[13]; const int* a01_c = (const int*)d_in[14]; const float* a01_v = (const float*)d_in[15];
    const int* a02_r = (const int*)d_in[16]; const int* a02_c = (const int*)d_in[17]; const float* a02_v = (const float*)d_in[18];
    const int* a03_r = (const int*)d_in[19]; const int* a03_c = (const int*)d_in[20]; const float* a03_v = (const float*)d_in[21];
    const float* W3 = (const float*)d_in[22];   const float* b3 = (const float*)d_in[23];
    const float* W1_2 = (const float*)d_in[24]; const float* b1_2 = (const float*)d_in[25];
    const float* W2_2 = (const float*)d_in[26]; const float* b2_2 = (const float*)d_in[27];
    const float* W3_2 = (const float*)d_in[28]; const float* b3_2 = (const float*)d_in[29];

    float* out = (float*)d_out;

    // CSR build: 4 launches
    k_zero<<<(CU_TOT + 255) / 256, 256>>>();
    k_hist_all<<<HB03, 256>>>(a11_r, a22_r, a33_r, a01_r, a02_r, a03_r);
    k_scan_all<<<6, 1024>>>();
    k_scatter_all<<<HB03, 256>>>(a11_r, a11_c, a11_v, a22_r, a22_c, a22_v,
                                 a33_r, a33_c, a33_v, a01_r, a01_c, a01_v,
                                 a02_r, a02_c, a02_v, a03_r, a03_c, a03_v);

    // compute: 5 launches
    k_stageA<<<3751, 256>>>(f1, f2, f3, W3, b3);
    k_stageB<<<946, 256>>>(W1_2, b1_2, W2_2, b2_2);
    k_stageC<<<3752, 256>>>(W3_2, b3_2);
    k_stageD<<<10629, 512>>>(wemb, out);
    k_stageE<<<625, 512>>>(out);
}